// round 2
// baseline (speedup 1.0000x reference)
#include <cuda_runtime.h>
#include <cuda_bf16.h>

#define KK   27
#define CIN  16
#define COUT 16
#define TPB  256
#define NODES_PER_BLOCK 256   // 32 nodes per warp, 8 warps

// ---- packed f32x2 helpers ----
__device__ __forceinline__ unsigned long long splat2(float v) {
    unsigned long long r;
    asm("mov.b64 %0, {%1, %1};" : "=l"(r) : "f"(v));
    return r;
}
__device__ __forceinline__ unsigned long long pack2(float lo, float hi) {
    unsigned long long r;
    asm("mov.b64 %0, {%1, %2};" : "=l"(r) : "f"(lo), "f"(hi));
    return r;
}
__device__ __forceinline__ void ffma2(unsigned long long& d,
                                      unsigned long long a,
                                      unsigned long long b) {
    asm("fma.rn.f32x2 %0, %1, %2, %0;" : "+l"(d) : "l"(a), "l"(b));
}
__device__ __forceinline__ unsigned long long addp2(unsigned long long a,
                                                    unsigned long long b) {
    unsigned long long r;
    asm("add.rn.f32x2 %0, %1, %2;" : "=l"(r) : "l"(a), "l"(b));
    return r;
}
// compile-time float4 component select (j constant under unroll)
__device__ __forceinline__ float getf(const float4& v, int j) {
    switch (j) { case 0: return v.x; case 1: return v.y;
                 case 2: return v.z; default: return v.w; }
}

// Y[i][o] = bias[o] + sum_k sum_c X[nbr[i][k]][c] * W[k][c][o]
//
// Lane l (m = l&3, g = l>>2): handles channels c in [4m,4m+4) for nodes
// {warpbase + 8b + g : b=0..3}. Gather round b: one LDG.128 per lane covers
// 8 full rows per warp instruction (1 L1tex wavefront per row).
// Epilogue: butterfly-reduce c-partials over the 4 lanes of each quad group.

__global__ __launch_bounds__(TPB, 2)
void conv_kernel(const float* __restrict__ x,       // [N_in, 16]
                 const float* __restrict__ w,       // [27, 16, 16]
                 const float* __restrict__ bias,    // [16]
                 const int*   __restrict__ nbr,     // [N_out, 27]
                 float*       __restrict__ out,     // [N_out, 16]
                 int n_out)
{
    __shared__ __align__(16) float ws[KK * CIN * COUT];   // 27648 B

    // Fill weights with quad rotation: quad q of row c stored at (q + (c>>2)) & 3.
    // Makes the 4 distinct rows {4m+j : m=0..3} touched by one LDS.128 hit
    // distinct bank-quads -> conflict-free broadcast.
    for (int i = threadIdx.x; i < KK * CIN * COUT; i += TPB) {
        int k = i >> 8;
        int c = (i >> 4) & 15;
        int o = i & 15;
        int q = o >> 2, e = o & 3;
        int po = (((q + (c >> 2)) & 3) << 2) | e;
        ws[((k * 16 + c) << 4) + po] = w[i];
    }
    __syncthreads();

    const int warp = threadIdx.x >> 5;
    const int lane = threadIdx.x & 31;
    const int warpbase = blockIdx.x * NODES_PER_BLOCK + warp * 32;
    if (warpbase >= n_out) return;
    const int m = lane & 3;
    const int g = lane >> 2;

    int mynode = warpbase + lane;
    if (mynode >= n_out) mynode = n_out - 1;
    const int* mynbr = nbr + (long long)mynode * KK;

    // acc[b][p]: packed outputs (2p, 2p+1) for node warpbase+8b+g,
    // partial over channels [4m, 4m+4), summed over all k.
    unsigned long long acc[4][8];
#pragma unroll
    for (int b = 0; b < 4; ++b)
#pragma unroll
        for (int p = 0; p < 8; ++p) acc[b][p] = 0ull;

    // prefetch k=0 gather
    float4 vcur[4];
    {
        int oi = __ldg(&mynbr[0]);
#pragma unroll
        for (int b = 0; b < 4; ++b) {
            int ridx = __shfl_sync(0xffffffffu, oi, 8 * b + g);
            vcur[b] = __ldg(reinterpret_cast<const float4*>(
                                x + (long long)ridx * CIN) + m);
        }
    }

#pragma unroll 1
    for (int k = 0; k < KK; ++k) {
        // prefetch k+1 (clamped; last iteration redundantly reloads k=26)
        float4 vnext[4];
        {
            int kn = (k + 1 < KK) ? (k + 1) : (KK - 1);
            int oi = __ldg(&mynbr[kn]);
#pragma unroll
            for (int b = 0; b < 4; ++b) {
                int ridx = __shfl_sync(0xffffffffu, oi, 8 * b + g);
                vnext[b] = __ldg(reinterpret_cast<const float4*>(
                                     x + (long long)ridx * CIN) + m);
            }
        }

        const float* wk = ws + k * (CIN * COUT);
#pragma unroll
        for (int j = 0; j < 4; ++j) {
            unsigned long long xs0 = splat2(getf(vcur[0], j));
            unsigned long long xs1 = splat2(getf(vcur[1], j));
            unsigned long long xs2 = splat2(getf(vcur[2], j));
            unsigned long long xs3 = splat2(getf(vcur[3], j));
            const float* wr = wk + ((m * 4 + j) << 4);   // row c = 4m+j
#pragma unroll
            for (int q = 0; q < 4; ++q) {
                ulonglong2 wp = *reinterpret_cast<const ulonglong2*>(
                    wr + (((q + m) & 3) << 2));          // de-rotate quad
                ffma2(acc[0][2 * q],     xs0, wp.x);
                ffma2(acc[0][2 * q + 1], xs0, wp.y);
                ffma2(acc[1][2 * q],     xs1, wp.x);
                ffma2(acc[1][2 * q + 1], xs1, wp.y);
                ffma2(acc[2][2 * q],     xs2, wp.x);
                ffma2(acc[2][2 * q + 1], xs2, wp.y);
                ffma2(acc[3][2 * q],     xs3, wp.x);
                ffma2(acc[3][2 * q + 1], xs3, wp.y);
            }
        }

#pragma unroll
        for (int b = 0; b < 4; ++b) vcur[b] = vnext[b];
    }

    // Epilogue: reduce c-partials across each quad group, add bias, store.
    float4 bv = __ldg(reinterpret_cast<const float4*>(bias) + m);
    unsigned long long bp0 = pack2(bv.x, bv.y);
    unsigned long long bp1 = pack2(bv.z, bv.w);

#pragma unroll
    for (int b = 0; b < 4; ++b) {
        int node = warpbase + 8 * b + g;
#pragma unroll
        for (int p = 0; p < 8; ++p) {
            unsigned long long v = acc[b][p];
            v = addp2(v, __shfl_xor_sync(0xffffffffu, v, 1));
            v = addp2(v, __shfl_xor_sync(0xffffffffu, v, 2));
            acc[b][p] = v;
        }
        // lane m stores output quad m (pairs 2m, 2m+1) -> coalesced STG.128
        unsigned long long o0 = addp2(acc[b][2 * m],     bp0);
        unsigned long long o1 = addp2(acc[b][2 * m + 1], bp1);
        if (node < n_out) {
            ulonglong2 st; st.x = o0; st.y = o1;
            *(reinterpret_cast<ulonglong2*>(out + (long long)node * COUT) + m) = st;
        }
    }
}

// level passthrough for any trailing output elements beyond N_out*16
__global__ void tail_kernel(const int* __restrict__ level,
                            float* __restrict__ out,
                            long long start, long long count)
{
    long long i = (long long)blockIdx.x * blockDim.x + threadIdx.x;
    if (i < count) out[start + i] = (float)(*level);
}

extern "C" void kernel_launch(void* const* d_in, const int* in_sizes, int n_in,
                              void* d_out, int out_size)
{
    const float* x    = (const float*)d_in[0];
    const float* w    = (const float*)d_in[1];
    const float* bias = (const float*)d_in[2];
    const int*   nbr  = (const int*)d_in[3];
    const int*   lvl  = (n_in > 4) ? (const int*)d_in[4] : nullptr;

    const int n_out = in_sizes[3] / KK;
    float* out = (float*)d_out;

    const int grid = (n_out + NODES_PER_BLOCK - 1) / NODES_PER_BLOCK;
    conv_kernel<<<grid, TPB>>>(x, w, bias, nbr, out, n_out);

    const long long conv_elems = (long long)n_out * COUT;
    if ((long long)out_size > conv_elems && lvl != nullptr) {
        long long rem = (long long)out_size - conv_elems;
        int tgrid = (int)((rem + 127) / 128);
        tail_kernel<<<tgrid, 128>>>(lvl, out, conv_elems, rem);
    }
}

// round 3
// speedup vs baseline: 1.0712x; 1.0712x over previous
#include <cuda_runtime.h>
#include <cuda_bf16.h>

#define KK   27
#define CIN  16
#define COUT 16
#define TPB  256
#define NPB  128            // nodes per block: 16 per warp, 8 warps
#define IDXS (NPB * KK)     // 3456 staged indices

// ---- packed f32x2 helpers ----
__device__ __forceinline__ unsigned long long splat2(float v) {
    unsigned long long r;
    asm("mov.b64 %0, {%1, %1};" : "=l"(r) : "f"(v));
    return r;
}
__device__ __forceinline__ unsigned long long pack2(float lo, float hi) {
    unsigned long long r;
    asm("mov.b64 %0, {%1, %2};" : "=l"(r) : "f"(lo), "f"(hi));
    return r;
}
__device__ __forceinline__ void ffma2(unsigned long long& d,
                                      unsigned long long a,
                                      unsigned long long b) {
    asm("fma.rn.f32x2 %0, %1, %2, %0;" : "+l"(d) : "l"(a), "l"(b));
}
__device__ __forceinline__ unsigned long long addp2(unsigned long long a,
                                                    unsigned long long b) {
    unsigned long long r;
    asm("add.rn.f32x2 %0, %1, %2;" : "=l"(r) : "l"(a), "l"(b));
    return r;
}
__device__ __forceinline__ float getf(const float4& v, int j) {
    switch (j) { case 0: return v.x; case 1: return v.y;
                 case 2: return v.z; default: return v.w; }
}

// Y[i][o] = bias[o] + sum_k sum_c X[nbr[i][k]][c] * W[k][c][o]
//
// Warp covers 16 nodes. Lane l (m=l&3 channel-quad, g=l>>2 node-selector):
// partial sums over channels [4m,4m+4) for nodes {warpbase+g, warpbase+8+g}.
// One LDG.128 per (thread,node,k): warp instruction covers 8 full 64B rows
// -> 8 L1tex wavefronts. Indices staged in smem (coalesced once per block).
// Epilogue: butterfly-reduce the 4 channel-quads per node, add bias, STG.128.

__global__ __launch_bounds__(TPB, 2)
void conv_kernel(const float* __restrict__ x,       // [N_in, 16]
                 const float* __restrict__ w,       // [27, 16, 16]
                 const float* __restrict__ bias,    // [16]
                 const int*   __restrict__ nbr,     // [N_out, 27]
                 float*       __restrict__ out,     // [N_out, 16]
                 int n_out,
                 const int*   __restrict__ lvl,     // level scalar (or null)
                 long long tail_start, int tail_count)
{
    __shared__ __align__(16) float ws[KK * CIN * COUT];   // 27648 B
    __shared__ int idxs[IDXS];                             // 13824 B

    // tail passthrough (flattened (out, level) tuple trailing elements)
    if (blockIdx.x == gridDim.x - 1 && lvl != nullptr &&
        (int)threadIdx.x < tail_count) {
        out[tail_start + threadIdx.x] = (float)(*lvl);
    }

    // Weights with quad rotation: quad q of row c stored at (q + (c>>2)) & 3,
    // so the 4 distinct rows {4m+j} of one LDS.128 hit distinct bank-quads.
    for (int i = threadIdx.x; i < KK * CIN * COUT; i += TPB) {
        int c = (i >> 4) & 15;
        int o = i & 15;
        int po = ((((o >> 2) + (c >> 2)) & 3) << 2) | (o & 3);
        ws[(i & ~15) + po] = w[i];
    }
    // Stage this block's neighbor indices (coalesced)
    {
        const int base = blockIdx.x * NPB;
        for (int i = threadIdx.x; i < IDXS; i += TPB) {
            int node = base + i / KK;
            int kk = i - (i / KK) * KK;
            if (node >= n_out) node = n_out - 1;
            idxs[i] = __ldg(&nbr[(long long)node * KK + kk]);
        }
    }
    __syncthreads();

    const int warp = threadIdx.x >> 5;
    const int lane = threadIdx.x & 31;
    const int warpbase = blockIdx.x * NPB + warp * 16;
    if (warpbase >= n_out) return;
    const int m = lane & 3;
    const int g = lane >> 2;

    const int l0 = (warp * 16 + g) * KK;          // smem idx row, node b=0
    const int l1 = (warp * 16 + 8 + g) * KK;      // node b=1

    unsigned long long acc0[8], acc1[8];
#pragma unroll
    for (int p = 0; p < 8; ++p) { acc0[p] = 0ull; acc1[p] = 0ull; }

    // prefetch k=0
    float4 vcur0, vcur1;
    {
        int j0 = idxs[l0], j1 = idxs[l1];
        vcur0 = __ldg(reinterpret_cast<const float4*>(x + (size_t)j0 * CIN) + m);
        vcur1 = __ldg(reinterpret_cast<const float4*>(x + (size_t)j1 * CIN) + m);
    }

#pragma unroll 1
    for (int k = 0; k < KK; ++k) {
        // prefetch k+1 (last iter redundantly reloads k=26)
        const int kn = (k + 1 < KK) ? (k + 1) : (KK - 1);
        const int jn0 = idxs[l0 + kn];
        const int jn1 = idxs[l1 + kn];
        float4 vn0 = __ldg(reinterpret_cast<const float4*>(x + (size_t)jn0 * CIN) + m);
        float4 vn1 = __ldg(reinterpret_cast<const float4*>(x + (size_t)jn1 * CIN) + m);

        const float* wk = ws + (k << 8);
#pragma unroll
        for (int j = 0; j < 4; ++j) {
            const unsigned long long xs0 = splat2(getf(vcur0, j));
            const unsigned long long xs1 = splat2(getf(vcur1, j));
            const float* wr = wk + ((4 * m + j) << 4);   // weight row c = 4m+j
#pragma unroll
            for (int q = 0; q < 4; ++q) {
                ulonglong2 wp = *reinterpret_cast<const ulonglong2*>(
                    wr + (((q + m) & 3) << 2));          // de-rotate quad
                ffma2(acc0[2 * q],     xs0, wp.x);
                ffma2(acc0[2 * q + 1], xs0, wp.y);
                ffma2(acc1[2 * q],     xs1, wp.x);
                ffma2(acc1[2 * q + 1], xs1, wp.y);
            }
        }
        vcur0 = vn0; vcur1 = vn1;
    }

    // Epilogue: reduce channel-quad partials across the 4 lanes of each group.
    float4 bv = __ldg(reinterpret_cast<const float4*>(bias) + m);
    const unsigned long long bp0 = pack2(bv.x, bv.y);
    const unsigned long long bp1 = pack2(bv.z, bv.w);

#pragma unroll
    for (int p = 0; p < 8; ++p) {
        unsigned long long v0 = acc0[p];
        v0 = addp2(v0, __shfl_xor_sync(0xffffffffu, v0, 1));
        v0 = addp2(v0, __shfl_xor_sync(0xffffffffu, v0, 2));
        acc0[p] = v0;
        unsigned long long v1 = acc1[p];
        v1 = addp2(v1, __shfl_xor_sync(0xffffffffu, v1, 1));
        v1 = addp2(v1, __shfl_xor_sync(0xffffffffu, v1, 2));
        acc1[p] = v1;
    }

    const int node0 = warpbase + g;
    if (node0 < n_out) {
        ulonglong2 st;
        st.x = addp2(acc0[2 * m], bp0);
        st.y = addp2(acc0[2 * m + 1], bp1);
        *(reinterpret_cast<ulonglong2*>(out + (long long)node0 * COUT) + m) = st;
    }
    const int node1 = warpbase + 8 + g;
    if (node1 < n_out) {
        ulonglong2 st;
        st.x = addp2(acc1[2 * m], bp0);
        st.y = addp2(acc1[2 * m + 1], bp1);
        *(reinterpret_cast<ulonglong2*>(out + (long long)node1 * COUT) + m) = st;
    }
}

extern "C" void kernel_launch(void* const* d_in, const int* in_sizes, int n_in,
                              void* d_out, int out_size)
{
    const float* x    = (const float*)d_in[0];
    const float* w    = (const float*)d_in[1];
    const float* bias = (const float*)d_in[2];
    const int*   nbr  = (const int*)d_in[3];
    const int*   lvl  = (n_in > 4) ? (const int*)d_in[4] : nullptr;

    const int n_out = in_sizes[3] / KK;
    float* out = (float*)d_out;

    const long long conv_elems = (long long)n_out * COUT;
    long long tail_start = conv_elems;
    int tail_count = 0;
    if ((long long)out_size > conv_elems && lvl != nullptr)
        tail_count = (int)((long long)out_size - conv_elems);

    const int grid = (n_out + NPB - 1) / NPB;
    conv_kernel<<<grid, TPB>>>(x, w, bias, nbr, out, n_out,
                               lvl, tail_start, tail_count);
}

// round 4
// speedup vs baseline: 1.1134x; 1.0394x over previous
#include <cuda_runtime.h>
#include <cuda_bf16.h>

#define KK   27
#define CIN  16
#define COUT 16
#define TPB  256
#define NPB  256            // nodes per block: 32 per warp, 8 warps
#define IDXS (NPB * KK)     // 6912 staged indices

// ---- packed f32x2 helpers ----
__device__ __forceinline__ unsigned long long splat2(float v) {
    unsigned long long r;
    asm("mov.b64 %0, {%1, %1};" : "=l"(r) : "f"(v));
    return r;
}
__device__ __forceinline__ unsigned long long pack2(float lo, float hi) {
    unsigned long long r;
    asm("mov.b64 %0, {%1, %2};" : "=l"(r) : "f"(lo), "f"(hi));
    return r;
}
__device__ __forceinline__ void ffma2(unsigned long long& d,
                                      unsigned long long a,
                                      unsigned long long b) {
    asm("fma.rn.f32x2 %0, %1, %2, %0;" : "+l"(d) : "l"(a), "l"(b));
}
__device__ __forceinline__ unsigned long long addp2(unsigned long long a,
                                                    unsigned long long b) {
    unsigned long long r;
    asm("add.rn.f32x2 %0, %1, %2;" : "=l"(r) : "l"(a), "l"(b));
    return r;
}
__device__ __forceinline__ float getf(const float4& v, int j) {
    switch (j) { case 0: return v.x; case 1: return v.y;
                 case 2: return v.z; default: return v.w; }
}

// Y[i][o] = bias[o] + sum_k sum_c X[nbr[i][k]][c] * W[k][c][o]
//
// Warp covers 32 nodes. Lane l (m=l&3 channel-quad, g=l>>2): partial sums
// over channels [4m,4m+4) for 4 nodes {warpbase+8b+g : b=0..3}.
// Weight smem traffic per node-k = 1024/P_t bytes; P_t=4 here (key lever).
// One LDG.128 per (thread,b,k): warp instruction covers 8 full 64B rows.

__global__ __launch_bounds__(TPB)
void conv_kernel(const float* __restrict__ x,       // [N_in, 16]
                 const float* __restrict__ w,       // [27, 16, 16]
                 const float* __restrict__ bias,    // [16]
                 const int*   __restrict__ nbr,     // [N_out, 27]
                 float*       __restrict__ out,     // [N_out, 16]
                 int n_out,
                 const int*   __restrict__ lvl,     // level scalar (or null)
                 long long tail_start, int tail_count)
{
    __shared__ __align__(16) float ws[KK * CIN * COUT];   // 27648 B
    __shared__ int idxs[IDXS];                             // 27648 B

    // tail passthrough (flattened (out, level) tuple trailing elements)
    if (blockIdx.x == gridDim.x - 1 && lvl != nullptr &&
        (int)threadIdx.x < tail_count) {
        out[tail_start + threadIdx.x] = (float)(*lvl);
    }

    // Weights with quad rotation: quad q of row c stored at (q + (c>>2)) & 3,
    // so the 4 distinct rows {4m+j} of one LDS.128 hit distinct bank-quads.
    for (int i = threadIdx.x; i < KK * CIN * COUT; i += TPB) {
        int c = (i >> 4) & 15;
        int o = i & 15;
        int po = ((((o >> 2) + (c >> 2)) & 3) << 2) | (o & 3);
        ws[(i & ~15) + po] = w[i];
    }
    // Stage this block's neighbor indices (coalesced)
    {
        const int base = blockIdx.x * NPB;
        for (int i = threadIdx.x; i < IDXS; i += TPB) {
            int node = base + i / KK;
            int kk = i - (i / KK) * KK;
            if (node >= n_out) node = n_out - 1;
            idxs[i] = __ldg(&nbr[(long long)node * KK + kk]);
        }
    }
    __syncthreads();

    const int warp = threadIdx.x >> 5;
    const int lane = threadIdx.x & 31;
    const int warpbase = blockIdx.x * NPB + warp * 32;
    if (warpbase >= n_out) return;
    const int m = lane & 3;
    const int g = lane >> 2;

    // smem index rows for the 4 nodes this thread accumulates
    int loff[4];
#pragma unroll
    for (int b = 0; b < 4; ++b) loff[b] = (warp * 32 + 8 * b + g) * KK;

    unsigned long long acc[4][8];
#pragma unroll
    for (int b = 0; b < 4; ++b)
#pragma unroll
        for (int p = 0; p < 8; ++p) acc[b][p] = 0ull;

    // prefetch k=0 gather (MLP=4)
    float4 vcur[4];
#pragma unroll
    for (int b = 0; b < 4; ++b) {
        int j = idxs[loff[b]];
        vcur[b] = __ldg(reinterpret_cast<const float4*>(x + (size_t)j * CIN) + m);
    }

#pragma unroll 1
    for (int k = 0; k < KK; ++k) {
        // prefetch k+1 (last iter redundantly reloads k=26)
        const int kn = (k + 1 < KK) ? (k + 1) : (KK - 1);
        float4 vnext[4];
#pragma unroll
        for (int b = 0; b < 4; ++b) {
            int j = idxs[loff[b] + kn];
            vnext[b] = __ldg(reinterpret_cast<const float4*>(x + (size_t)j * CIN) + m);
        }

        const float* wk = ws + (k << 8);
#pragma unroll
        for (int j = 0; j < 4; ++j) {
            const unsigned long long xs0 = splat2(getf(vcur[0], j));
            const unsigned long long xs1 = splat2(getf(vcur[1], j));
            const unsigned long long xs2 = splat2(getf(vcur[2], j));
            const unsigned long long xs3 = splat2(getf(vcur[3], j));
            const float* wr = wk + ((4 * m + j) << 4);   // weight row c = 4m+j
#pragma unroll
            for (int q = 0; q < 4; ++q) {
                ulonglong2 wp = *reinterpret_cast<const ulonglong2*>(
                    wr + (((q + m) & 3) << 2));          // de-rotate quad
                ffma2(acc[0][2 * q],     xs0, wp.x);
                ffma2(acc[0][2 * q + 1], xs0, wp.y);
                ffma2(acc[1][2 * q],     xs1, wp.x);
                ffma2(acc[1][2 * q + 1], xs1, wp.y);
                ffma2(acc[2][2 * q],     xs2, wp.x);
                ffma2(acc[2][2 * q + 1], xs2, wp.y);
                ffma2(acc[3][2 * q],     xs3, wp.x);
                ffma2(acc[3][2 * q + 1], xs3, wp.y);
            }
        }
#pragma unroll
        for (int b = 0; b < 4; ++b) vcur[b] = vnext[b];
    }

    // Epilogue: butterfly-reduce channel-quad partials, add bias, STG.128.
    float4 bv = __ldg(reinterpret_cast<const float4*>(bias) + m);
    const unsigned long long bp0 = pack2(bv.x, bv.y);
    const unsigned long long bp1 = pack2(bv.z, bv.w);

#pragma unroll
    for (int b = 0; b < 4; ++b) {
#pragma unroll
        for (int p = 0; p < 8; ++p) {
            unsigned long long v = acc[b][p];
            v = addp2(v, __shfl_xor_sync(0xffffffffu, v, 1));
            v = addp2(v, __shfl_xor_sync(0xffffffffu, v, 2));
            acc[b][p] = v;
        }
        const int node = warpbase + 8 * b + g;
        if (node < n_out) {
            ulonglong2 st;
            st.x = addp2(acc[b][2 * m],     bp0);
            st.y = addp2(acc[b][2 * m + 1], bp1);
            *(reinterpret_cast<ulonglong2*>(out + (long long)node * COUT) + m) = st;
        }
    }
}

extern "C" void kernel_launch(void* const* d_in, const int* in_sizes, int n_in,
                              void* d_out, int out_size)
{
    const float* x    = (const float*)d_in[0];
    const float* w    = (const float*)d_in[1];
    const float* bias = (const float*)d_in[2];
    const int*   nbr  = (const int*)d_in[3];
    const int*   lvl  = (n_in > 4) ? (const int*)d_in[4] : nullptr;

    const int n_out = in_sizes[3] / KK;
    float* out = (float*)d_out;

    const long long conv_elems = (long long)n_out * COUT;
    long long tail_start = conv_elems;
    int tail_count = 0;
    if ((long long)out_size > conv_elems && lvl != nullptr)
        tail_count = (int)((long long)out_size - conv_elems);

    const int grid = (n_out + NPB - 1) / NPB;
    conv_kernel<<<grid, TPB>>>(x, w, bias, nbr, out, n_out,
                               lvl, tail_start, tail_count);
}

// round 6
// speedup vs baseline: 1.4826x; 1.3316x over previous
#include <cuda_runtime.h>
#include <cstdint>

#define KK   27
#define TPB  128
#define NPB  128            // nodes per block: 32 per warp, 4 warps

typedef unsigned long long ull;

// ---- packed f32x2 helpers ----
__device__ __forceinline__ ull splat2(float v) {
    ull r; asm("mov.b64 %0, {%1, %1};" : "=l"(r) : "f"(v)); return r;
}
__device__ __forceinline__ ull pack2(float lo, float hi) {
    ull r; asm("mov.b64 %0, {%1, %2};" : "=l"(r) : "f"(lo), "f"(hi)); return r;
}
__device__ __forceinline__ void ffma2(ull& d, ull a, ull b) {
    asm("fma.rn.f32x2 %0, %1, %2, %0;" : "+l"(d) : "l"(a), "l"(b));
}
__device__ __forceinline__ ull addp2(ull a, ull b) {
    ull r; asm("add.rn.f32x2 %0, %1, %2;" : "=l"(r) : "l"(a), "l"(b)); return r;
}
__device__ __forceinline__ float getf(const float4& v, int j) {
    switch (j) { case 0: return v.x; case 1: return v.y;
                 case 2: return v.z; default: return v.w; }
}

// Y[i][o] = bias[o] + sum_k sum_c X[nbr[i][k]][c] * W[k][c][o]
//
// Lane l: m = l&3 (channel-quad), h = (l>>2)&1 (output-half, outs 8h..8h+7),
// ns = l>>3 (node octet). Lane accumulates partial sums over channels
// [4m,4m+4) x outputs [8h,8h+8) for 8 nodes.  Weight bytes per lane per k =
// 128B -> 16 cyc/warp-k LDS serving 32 nodes (R4 paid 64).  Gather: one
// LDG.128 per (lane,node,k); h-duplicate addresses dedup in the coalescer ->
// 1 L1tex wavefront per input row.  Epilogue: butterfly over the 4 m-lanes.

__global__ __launch_bounds__(TPB)
void conv_kernel(const float* __restrict__ x,       // [N_in, 16]
                 const float* __restrict__ w,       // [27, 16, 16]
                 const float* __restrict__ bias,    // [16]
                 const int*   __restrict__ nbr,     // [N_out, 27]
                 float*       __restrict__ out,     // [N_out, 16]
                 int n_out,
                 const int*   __restrict__ lvl,
                 long long tail_start, int tail_count)
{
    __shared__ __align__(16) float ws[KK * 256];    // 27648 B, permuted
    __shared__ __align__(16) int idxT[KK * NPB];    // 13824 B, [k][node]

    // tail passthrough for flattened (out, level) tuple
    if (blockIdx.x == 0 && lvl != nullptr && (int)threadIdx.x < tail_count)
        out[tail_start + threadIdx.x] = (float)(*lvl);

    // Stage weights permuted: ws[k*256 + jj*64 + (m+4h)*8 + e]
    //   = w[k][4m+jj][8h+e],  jj=c&3, m=c>>2, h=o>>3, e=o&7.
    // One LDS.128 per (jj, pair-half) then serves all 8 (m,h) lanes with
    // distinct 16B segments.
    for (int i = threadIdx.x; i < KK * 256; i += TPB) {
        int k = i >> 8, c = (i >> 4) & 15, o = i & 15;
        ws[k * 256 + (c & 3) * 64 + ((c >> 2) + 4 * (o >> 3)) * 8 + (o & 7)]
            = w[i];
    }
    // Stage indices transposed: idxT[k][node_local] (coalesced gmem reads)
    const int base = blockIdx.x * NPB;
    for (int i = threadIdx.x; i < KK * NPB; i += TPB) {
        int nl = i / KK, kk = i - nl * KK;
        int node = base + nl;
        if (node >= n_out) node = n_out - 1;
        idxT[kk * NPB + nl] = __ldg(&nbr[(long long)node * KK + kk]);
    }
    __syncthreads();

    const int warp = threadIdx.x >> 5;
    const int lane = threadIdx.x & 31;
    const int warpbase = base + warp * 32;
    if (warpbase >= n_out) return;
    const int m  = lane & 3;
    const int h  = (lane >> 2) & 1;
    const int ns = lane >> 3;
    const int nlb = warp * 32 + ns * 8;             // local node base (8)

    ull acc[8][4];                                   // [node][out-pair]
#pragma unroll
    for (int j = 0; j < 8; ++j)
#pragma unroll
        for (int p = 0; p < 4; ++p) acc[j][p] = 0ull;

    // prefetch k=0 gather (8-deep MLP)
    float4 xc[8];
    {
        int4 ia = *reinterpret_cast<const int4*>(idxT + nlb);
        int4 ib = *reinterpret_cast<const int4*>(idxT + nlb + 4);
        xc[0] = __ldg(reinterpret_cast<const float4*>(x + (size_t)ia.x * 16) + m);
        xc[1] = __ldg(reinterpret_cast<const float4*>(x + (size_t)ia.y * 16) + m);
        xc[2] = __ldg(reinterpret_cast<const float4*>(x + (size_t)ia.z * 16) + m);
        xc[3] = __ldg(reinterpret_cast<const float4*>(x + (size_t)ia.w * 16) + m);
        xc[4] = __ldg(reinterpret_cast<const float4*>(x + (size_t)ib.x * 16) + m);
        xc[5] = __ldg(reinterpret_cast<const float4*>(x + (size_t)ib.y * 16) + m);
        xc[6] = __ldg(reinterpret_cast<const float4*>(x + (size_t)ib.z * 16) + m);
        xc[7] = __ldg(reinterpret_cast<const float4*>(x + (size_t)ib.w * 16) + m);
    }

#pragma unroll 1
    for (int k = 0; k < KK; ++k) {
        // prefetch k+1 (last iter redundantly reloads k=26)
        const int kn = (k + 1 < KK) ? (k + 1) : (KK - 1);
        float4 xn[8];
        {
            int4 ia = *reinterpret_cast<const int4*>(idxT + kn * NPB + nlb);
            int4 ib = *reinterpret_cast<const int4*>(idxT + kn * NPB + nlb + 4);
            xn[0] = __ldg(reinterpret_cast<const float4*>(x + (size_t)ia.x * 16) + m);
            xn[1] = __ldg(reinterpret_cast<const float4*>(x + (size_t)ia.y * 16) + m);
            xn[2] = __ldg(reinterpret_cast<const float4*>(x + (size_t)ia.z * 16) + m);
            xn[3] = __ldg(reinterpret_cast<const float4*>(x + (size_t)ia.w * 16) + m);
            xn[4] = __ldg(reinterpret_cast<const float4*>(x + (size_t)ib.x * 16) + m);
            xn[5] = __ldg(reinterpret_cast<const float4*>(x + (size_t)ib.y * 16) + m);
            xn[6] = __ldg(reinterpret_cast<const float4*>(x + (size_t)ib.z * 16) + m);
            xn[7] = __ldg(reinterpret_cast<const float4*>(x + (size_t)ib.w * 16) + m);
        }

        const float* wk = ws + k * 256 + (m + 4 * h) * 8;
#pragma unroll
        for (int jj = 0; jj < 4; ++jj) {
            // weight pairs for channel c=4m+jj, outs 8h..8h+7 (4 pairs)
            ulonglong2 wA = *reinterpret_cast<const ulonglong2*>(wk + jj * 64);
            ulonglong2 wB = *reinterpret_cast<const ulonglong2*>(wk + jj * 64 + 4);
#pragma unroll
            for (int j = 0; j < 8; ++j) {
                const ull a = splat2(getf(xc[j], jj));
                ffma2(acc[j][0], a, wA.x);
                ffma2(acc[j][1], a, wA.y);
                ffma2(acc[j][2], a, wB.x);
                ffma2(acc[j][3], a, wB.y);
            }
        }
#pragma unroll
        for (int j = 0; j < 8; ++j) xc[j] = xn[j];
    }

    // Epilogue: reduce channel-quad partials over the 4 m-lanes, add bias.
    float4 b0 = __ldg(reinterpret_cast<const float4*>(bias) + 2 * h);
    float4 b1 = __ldg(reinterpret_cast<const float4*>(bias) + 2 * h + 1);
    ull bp[4] = { pack2(b0.x, b0.y), pack2(b0.z, b0.w),
                  pack2(b1.x, b1.y), pack2(b1.z, b1.w) };

#pragma unroll
    for (int j = 0; j < 8; ++j) {
#pragma unroll
        for (int p = 0; p < 4; ++p) {
            ull v = acc[j][p];
            v = addp2(v, __shfl_xor_sync(0xffffffffu, v, 1));
            v = addp2(v, __shfl_xor_sync(0xffffffffu, v, 2));
            acc[j][p] = v;
        }
        const int node = warpbase + ns * 8 + j;
        if (m == 0 && node < n_out) {
            ulonglong2* op = reinterpret_cast<ulonglong2*>(
                out + (long long)node * 16 + 8 * h);
            ulonglong2 s0; s0.x = addp2(acc[j][0], bp[0]);
                           s0.y = addp2(acc[j][1], bp[1]);
            ulonglong2 s1; s1.x = addp2(acc[j][2], bp[2]);
                           s1.y = addp2(acc[j][3], bp[3]);
            op[0] = s0;
            op[1] = s1;
        }
    }
}

extern "C" void kernel_launch(void* const* d_in, const int* in_sizes, int n_in,
                              void* d_out, int out_size)
{
    const float* x    = (const float*)d_in[0];
    const float* w    = (const float*)d_in[1];
    const float* bias = (const float*)d_in[2];
    const int*   nbr  = (const int*)d_in[3];
    const int*   lvl  = (n_in > 4) ? (const int*)d_in[4] : nullptr;

    const int n_out = in_sizes[3] / KK;
    float* out = (float*)d_out;

    const long long conv_elems = (long long)n_out * 16;
    long long tail_start = conv_elems;
    int tail_count = 0;
    if ((long long)out_size > conv_elems && lvl != nullptr)
        tail_count = (int)((long long)out_size - conv_elems);

    const int grid = (n_out + NPB - 1) / NPB;
    conv_kernel<<<grid, TPB>>>(x, w, bias, nbr, out, n_out,
                               lvl, tail_start, tail_count);
}

// round 7
// speedup vs baseline: 1.5129x; 1.0204x over previous
#include <cuda_runtime.h>
#include <cstdint>

#define KK   27
#define TPB  128
#define NPB  128            // nodes per block: 32 per warp, 4 warps

typedef unsigned long long ull;

// ---- packed f32x2 helpers ----
__device__ __forceinline__ ull splat2(float v) {
    ull r; asm("mov.b64 %0, {%1, %1};" : "=l"(r) : "f"(v)); return r;
}
__device__ __forceinline__ ull pack2(float lo, float hi) {
    ull r; asm("mov.b64 %0, {%1, %2};" : "=l"(r) : "f"(lo), "f"(hi)); return r;
}
__device__ __forceinline__ void ffma2(ull& d, ull a, ull b) {
    asm("fma.rn.f32x2 %0, %1, %2, %0;" : "+l"(d) : "l"(a), "l"(b));
}
__device__ __forceinline__ ull addp2(ull a, ull b) {
    ull r; asm("add.rn.f32x2 %0, %1, %2;" : "=l"(r) : "l"(a), "l"(b)); return r;
}
__device__ __forceinline__ float getf(const float4& v, int j) {
    switch (j) { case 0: return v.x; case 1: return v.y;
                 case 2: return v.z; default: return v.w; }
}

// Y[i][o] = bias[o] + sum_k sum_c X[nbr[i][k]][c] * W[k][c][o]
//
// Lane l: m = l&3 (channel-quad), h = (l>>2)&1 (output-half), ns = l>>3
// (node octet). Lane accumulates partials over channels [4m,4m+4) x outputs
// [8h,8h+8) for 8 nodes.
//
// Weight smem layout (R7 fix): per (k, jj) a 256B group; first 128B holds the
// 8 lane-classes' A-quads (outs 8h..8h+3) at 16B stride, second 128B the
// B-quads (outs 8h+4..8h+7). Lane-class q = m+4h reads at q*16B -> the 8
// distinct addresses hit 8 distinct bank-quads, broadcast across the 4
// ns-duplicates => conflict-free LDS.128 (R6 layout was 2-way conflicted).

__global__ __launch_bounds__(TPB)
void conv_kernel(const float* __restrict__ x,       // [N_in, 16]
                 const float* __restrict__ w,       // [27, 16, 16]
                 const float* __restrict__ bias,    // [16]
                 const int*   __restrict__ nbr,     // [N_out, 27]
                 float*       __restrict__ out,     // [N_out, 16]
                 int n_out,
                 const int*   __restrict__ lvl,
                 long long tail_start, int tail_count)
{
    __shared__ __align__(16) float ws[KK * 256];    // 27648 B, permuted
    __shared__ __align__(16) int idxT[KK * NPB];    // 13824 B, [k][node]

    // tail passthrough for flattened (out, level) tuple
    if (blockIdx.x == 0 && lvl != nullptr && (int)threadIdx.x < tail_count)
        out[tail_start + threadIdx.x] = (float)(*lvl);

    // Stage weights permuted:
    //   i = k*256 + c*16 + o;  jj=c&3, m=c>>2, h=o>>3, e=o&7, q=m+4h
    //   ws[k*256 + jj*64 + (e>>2)*32 + q*4 + (e&3)] = w[i]
    for (int i = threadIdx.x; i < KK * 256; i += TPB) {
        int k = i >> 8, c = (i >> 4) & 15, o = i & 15;
        int jj = c & 3, q = (c >> 2) + 4 * (o >> 3), e = o & 7;
        ws[k * 256 + jj * 64 + (e >> 2) * 32 + q * 4 + (e & 3)] = w[i];
    }
    // Stage indices transposed: idxT[k][node_local] (coalesced gmem reads)
    const int base = blockIdx.x * NPB;
    for (int i = threadIdx.x; i < KK * NPB; i += TPB) {
        int nl = i / KK, kk = i - nl * KK;
        int node = base + nl;
        if (node >= n_out) node = n_out - 1;
        idxT[kk * NPB + nl] = __ldg(&nbr[(long long)node * KK + kk]);
    }
    __syncthreads();

    const int warp = threadIdx.x >> 5;
    const int lane = threadIdx.x & 31;
    const int warpbase = base + warp * 32;
    if (warpbase >= n_out) return;
    const int m  = lane & 3;
    const int h  = (lane >> 2) & 1;
    const int ns = lane >> 3;
    const int nlb = warp * 32 + ns * 8;             // local node base (8)
    const int q4 = (m + 4 * h) * 4;                 // lane-class float offset

    ull acc[8][4];                                   // [node][out-pair]
#pragma unroll
    for (int j = 0; j < 8; ++j)
#pragma unroll
        for (int p = 0; p < 4; ++p) acc[j][p] = 0ull;

    // prefetch k=0 gather (8-deep MLP)
    float4 xc[8];
    {
        int4 ia = *reinterpret_cast<const int4*>(idxT + nlb);
        int4 ib = *reinterpret_cast<const int4*>(idxT + nlb + 4);
        xc[0] = __ldg(reinterpret_cast<const float4*>(x + (size_t)ia.x * 16) + m);
        xc[1] = __ldg(reinterpret_cast<const float4*>(x + (size_t)ia.y * 16) + m);
        xc[2] = __ldg(reinterpret_cast<const float4*>(x + (size_t)ia.z * 16) + m);
        xc[3] = __ldg(reinterpret_cast<const float4*>(x + (size_t)ia.w * 16) + m);
        xc[4] = __ldg(reinterpret_cast<const float4*>(x + (size_t)ib.x * 16) + m);
        xc[5] = __ldg(reinterpret_cast<const float4*>(x + (size_t)ib.y * 16) + m);
        xc[6] = __ldg(reinterpret_cast<const float4*>(x + (size_t)ib.z * 16) + m);
        xc[7] = __ldg(reinterpret_cast<const float4*>(x + (size_t)ib.w * 16) + m);
    }

#pragma unroll 1
    for (int k = 0; k < KK; ++k) {
        // prefetch k+1 (last iter redundantly reloads k=26)
        const int kn = (k + 1 < KK) ? (k + 1) : (KK - 1);
        float4 xn[8];
        {
            int4 ia = *reinterpret_cast<const int4*>(idxT + kn * NPB + nlb);
            int4 ib = *reinterpret_cast<const int4*>(idxT + kn * NPB + nlb + 4);
            xn[0] = __ldg(reinterpret_cast<const float4*>(x + (size_t)ia.x * 16) + m);
            xn[1] = __ldg(reinterpret_cast<const float4*>(x + (size_t)ia.y * 16) + m);
            xn[2] = __ldg(reinterpret_cast<const float4*>(x + (size_t)ia.z * 16) + m);
            xn[3] = __ldg(reinterpret_cast<const float4*>(x + (size_t)ia.w * 16) + m);
            xn[4] = __ldg(reinterpret_cast<const float4*>(x + (size_t)ib.x * 16) + m);
            xn[5] = __ldg(reinterpret_cast<const float4*>(x + (size_t)ib.y * 16) + m);
            xn[6] = __ldg(reinterpret_cast<const float4*>(x + (size_t)ib.z * 16) + m);
            xn[7] = __ldg(reinterpret_cast<const float4*>(x + (size_t)ib.w * 16) + m);
        }

        const float* wk = ws + k * 256 + q4;
#pragma unroll
        for (int jj = 0; jj < 4; ++jj) {
            // conflict-free: lanes read at q*16B within a 128B row
            ulonglong2 wA = *reinterpret_cast<const ulonglong2*>(wk + jj * 64);
            ulonglong2 wB = *reinterpret_cast<const ulonglong2*>(wk + jj * 64 + 32);
#pragma unroll
            for (int j = 0; j < 8; ++j) {
                const ull a = splat2(getf(xc[j], jj));
                ffma2(acc[j][0], a, wA.x);
                ffma2(acc[j][1], a, wA.y);
                ffma2(acc[j][2], a, wB.x);
                ffma2(acc[j][3], a, wB.y);
            }
        }
#pragma unroll
        for (int j = 0; j < 8; ++j) xc[j] = xn[j];
    }

    // Epilogue: reduce channel-quad partials over the 4 m-lanes, add bias.
    float4 b0 = __ldg(reinterpret_cast<const float4*>(bias) + 2 * h);
    float4 b1 = __ldg(reinterpret_cast<const float4*>(bias) + 2 * h + 1);
    ull bp[4] = { pack2(b0.x, b0.y), pack2(b0.z, b0.w),
                  pack2(b1.x, b1.y), pack2(b1.z, b1.w) };

#pragma unroll
    for (int j = 0; j < 8; ++j) {
#pragma unroll
        for (int p = 0; p < 4; ++p) {
            ull v = acc[j][p];
            v = addp2(v, __shfl_xor_sync(0xffffffffu, v, 1));
            v = addp2(v, __shfl_xor_sync(0xffffffffu, v, 2));
            acc[j][p] = v;
        }
        const int node = warpbase + ns * 8 + j;
        if (m == 0 && node < n_out) {
            ulonglong2* op = reinterpret_cast<ulonglong2*>(
                out + (long long)node * 16 + 8 * h);
            ulonglong2 s0; s0.x = addp2(acc[j][0], bp[0]);
                           s0.y = addp2(acc[j][1], bp[1]);
            ulonglong2 s1; s1.x = addp2(acc[j][2], bp[2]);
                           s1.y = addp2(acc[j][3], bp[3]);
            op[0] = s0;
            op[1] = s1;
        }
    }
}

extern "C" void kernel_launch(void* const* d_in, const int* in_sizes, int n_in,
                              void* d_out, int out_size)
{
    const float* x    = (const float*)d_in[0];
    const float* w    = (const float*)d_in[1];
    const float* bias = (const float*)d_in[2];
    const int*   nbr  = (const int*)d_in[3];
    const int*   lvl  = (n_in > 4) ? (const int*)d_in[4] : nullptr;

    const int n_out = in_sizes[3] / KK;
    float* out = (float*)d_out;

    const long long conv_elems = (long long)n_out * 16;
    long long tail_start = conv_elems;
    int tail_count = 0;
    if ((long long)out_size > conv_elems && lvl != nullptr)
        tail_count = (int)((long long)out_size - conv_elems);

    const int grid = (n_out + NPB - 1) / NPB;
    conv_kernel<<<grid, TPB>>>(x, w, bias, nbr, out, n_out,
                               lvl, tail_start, tail_count);
}

// round 8
// speedup vs baseline: 1.6583x; 1.0961x over previous
#include <cuda_runtime.h>
#include <cstdint>

#define KK   27
#define TPB  128
#define NPB  128            // nodes per block: 32 per warp, 4 warps

typedef unsigned long long ull;

// ---- packed f32x2 helpers ----
__device__ __forceinline__ ull splat2(float v) {
    ull r; asm("mov.b64 %0, {%1, %1};" : "=l"(r) : "f"(v)); return r;
}
__device__ __forceinline__ ull pack2(float lo, float hi) {
    ull r; asm("mov.b64 %0, {%1, %2};" : "=l"(r) : "f"(lo), "f"(hi)); return r;
}
__device__ __forceinline__ void ffma2(ull& d, ull a, ull b) {
    asm("fma.rn.f32x2 %0, %1, %2, %0;" : "+l"(d) : "l"(a), "l"(b));
}
__device__ __forceinline__ ull addp2(ull a, ull b) {
    ull r; asm("add.rn.f32x2 %0, %1, %2;" : "=l"(r) : "l"(a), "l"(b)); return r;
}
__device__ __forceinline__ float getf(const float4& v, int j) {
    switch (j) { case 0: return v.x; case 1: return v.y;
                 case 2: return v.z; default: return v.w; }
}

// Y[i][o] = bias[o] + sum_k sum_c X[nbr[i][k]][c] * W[k][c][o]
//
// Lane l: m = l&3 (channel-quad), h = (l>>2)&1 (output-half), ns = l>>3
// (node octet). Lane accumulates partials over channels [4m,4m+4) x outputs
// [8h,8h+8) for 8 nodes.
//
// R8: gather via __ldcg (L2-only; x's 32MB random working set never hits the
// 228KB L1, so L1 line fills were pure overhead ~1/3 of L1 busy). Register
// double-buffer dropped; loads issue at top of each k-iteration with MLP=8,
// latency covered by 16 warps/SM (launch_bounds cap 128 regs -> 4 blocks).

__global__ __launch_bounds__(TPB, 4)
void conv_kernel(const float* __restrict__ x,       // [N_in, 16]
                 const float* __restrict__ w,       // [27, 16, 16]
                 const float* __restrict__ bias,    // [16]
                 const int*   __restrict__ nbr,     // [N_out, 27]
                 float*       __restrict__ out,     // [N_out, 16]
                 int n_out,
                 const int*   __restrict__ lvl,
                 long long tail_start, int tail_count)
{
    __shared__ __align__(16) float ws[KK * 256];    // 27648 B, permuted
    __shared__ __align__(16) int idxT[KK * NPB];    // 13824 B, [k][node]

    // tail passthrough for flattened (out, level) tuple
    if (blockIdx.x == 0 && lvl != nullptr && (int)threadIdx.x < tail_count)
        out[tail_start + threadIdx.x] = (float)(*lvl);

    // Stage weights permuted (conflict-free 16B-stride lane classes):
    //   i = k*256 + c*16 + o;  jj=c&3, q=(c>>2)+4*(o>>3), e=o&7
    //   ws[k*256 + jj*64 + (e>>2)*32 + q*4 + (e&3)] = w[i]
    for (int i = threadIdx.x; i < KK * 256; i += TPB) {
        int k = i >> 8, c = (i >> 4) & 15, o = i & 15;
        int jj = c & 3, q = (c >> 2) + 4 * (o >> 3), e = o & 7;
        ws[k * 256 + jj * 64 + (e >> 2) * 32 + q * 4 + (e & 3)] = w[i];
    }
    // Stage indices transposed: idxT[k][node_local] (coalesced gmem reads)
    const int base = blockIdx.x * NPB;
    for (int i = threadIdx.x; i < KK * NPB; i += TPB) {
        int nl = i / KK, kk = i - nl * KK;
        int node = base + nl;
        if (node >= n_out) node = n_out - 1;
        idxT[kk * NPB + nl] = __ldcg(&nbr[(long long)node * KK + kk]);
    }
    __syncthreads();

    const int warp = threadIdx.x >> 5;
    const int lane = threadIdx.x & 31;
    const int warpbase = base + warp * 32;
    if (warpbase >= n_out) return;
    const int m  = lane & 3;
    const int h  = (lane >> 2) & 1;
    const int ns = lane >> 3;
    const int nlb = warp * 32 + ns * 8;             // local node base (8)
    const int q4 = (m + 4 * h) * 4;                 // lane-class float offset

    ull acc[8][4];                                   // [node][out-pair]
#pragma unroll
    for (int j = 0; j < 8; ++j)
#pragma unroll
        for (int p = 0; p < 4; ++p) acc[j][p] = 0ull;

#pragma unroll 1
    for (int k = 0; k < KK; ++k) {
        // gather this k's 8 rows (MLP=8, L2-only caching)
        float4 xc[8];
        {
            int4 ia = *reinterpret_cast<const int4*>(idxT + k * NPB + nlb);
            int4 ib = *reinterpret_cast<const int4*>(idxT + k * NPB + nlb + 4);
            xc[0] = __ldcg(reinterpret_cast<const float4*>(x + (size_t)ia.x * 16) + m);
            xc[1] = __ldcg(reinterpret_cast<const float4*>(x + (size_t)ia.y * 16) + m);
            xc[2] = __ldcg(reinterpret_cast<const float4*>(x + (size_t)ia.z * 16) + m);
            xc[3] = __ldcg(reinterpret_cast<const float4*>(x + (size_t)ia.w * 16) + m);
            xc[4] = __ldcg(reinterpret_cast<const float4*>(x + (size_t)ib.x * 16) + m);
            xc[5] = __ldcg(reinterpret_cast<const float4*>(x + (size_t)ib.y * 16) + m);
            xc[6] = __ldcg(reinterpret_cast<const float4*>(x + (size_t)ib.z * 16) + m);
            xc[7] = __ldcg(reinterpret_cast<const float4*>(x + (size_t)ib.w * 16) + m);
        }

        const float* wk = ws + k * 256 + q4;
#pragma unroll
        for (int jj = 0; jj < 4; ++jj) {
            // conflict-free: lanes read at q*16B within a 128B row
            ulonglong2 wA = *reinterpret_cast<const ulonglong2*>(wk + jj * 64);
            ulonglong2 wB = *reinterpret_cast<const ulonglong2*>(wk + jj * 64 + 32);
#pragma unroll
            for (int j = 0; j < 8; ++j) {
                const ull a = splat2(getf(xc[j], jj));
                ffma2(acc[j][0], a, wA.x);
                ffma2(acc[j][1], a, wA.y);
                ffma2(acc[j][2], a, wB.x);
                ffma2(acc[j][3], a, wB.y);
            }
        }
    }

    // Epilogue: reduce channel-quad partials over the 4 m-lanes, add bias.
    float4 b0 = __ldg(reinterpret_cast<const float4*>(bias) + 2 * h);
    float4 b1 = __ldg(reinterpret_cast<const float4*>(bias) + 2 * h + 1);
    ull bp[4] = { pack2(b0.x, b0.y), pack2(b0.z, b0.w),
                  pack2(b1.x, b1.y), pack2(b1.z, b1.w) };

#pragma unroll
    for (int j = 0; j < 8; ++j) {
#pragma unroll
        for (int p = 0; p < 4; ++p) {
            ull v = acc[j][p];
            v = addp2(v, __shfl_xor_sync(0xffffffffu, v, 1));
            v = addp2(v, __shfl_xor_sync(0xffffffffu, v, 2));
            acc[j][p] = v;
        }
        const int node = warpbase + ns * 8 + j;
        if (m == 0 && node < n_out) {
            ulonglong2* op = reinterpret_cast<ulonglong2*>(
                out + (long long)node * 16 + 8 * h);
            ulonglong2 s0; s0.x = addp2(acc[j][0], bp[0]);
                           s0.y = addp2(acc[j][1], bp[1]);
            ulonglong2 s1; s1.x = addp2(acc[j][2], bp[2]);
                           s1.y = addp2(acc[j][3], bp[3]);
            op[0] = s0;
            op[1] = s1;
        }
    }
}

extern "C" void kernel_launch(void* const* d_in, const int* in_sizes, int n_in,
                              void* d_out, int out_size)
{
    const float* x    = (const float*)d_in[0];
    const float* w    = (const float*)d_in[1];
    const float* bias = (const float*)d_in[2];
    const int*   nbr  = (const int*)d_in[3];
    const int*   lvl  = (n_in > 4) ? (const int*)d_in[4] : nullptr;

    const int n_out = in_sizes[3] / KK;
    float* out = (float*)d_out;

    const long long conv_elems = (long long)n_out * 16;
    long long tail_start = conv_elems;
    int tail_count = 0;
    if ((long long)out_size > conv_elems && lvl != nullptr)
        tail_count = (int)((long long)out_size - conv_elems);

    const int grid = (n_out + NPB - 1) / NPB;
    conv_kernel<<<grid, TPB>>>(x, w, bias, nbr, out, n_out,
                               lvl, tail_start, tail_count);
}

// round 10
// speedup vs baseline: 1.6625x; 1.0025x over previous
#include <cuda_runtime.h>
#include <cstdint>

#define KK   27
#define TPB  128
#define NPB  128            // nodes per block: 32 per warp, 4 warps

typedef unsigned long long ull;

// ---- packed f32x2 helpers ----
__device__ __forceinline__ ull splat2(float v) {
    ull r; asm("mov.b64 %0, {%1, %1};" : "=l"(r) : "f"(v)); return r;
}
__device__ __forceinline__ ull pack2(float lo, float hi) {
    ull r; asm("mov.b64 %0, {%1, %2};" : "=l"(r) : "f"(lo), "f"(hi)); return r;
}
__device__ __forceinline__ void ffma2(ull& d, ull a, ull b) {
    asm("fma.rn.f32x2 %0, %1, %2, %0;" : "+l"(d) : "l"(a), "l"(b));
}
__device__ __forceinline__ ull addp2(ull a, ull b) {
    ull r; asm("add.rn.f32x2 %0, %1, %2;" : "=l"(r) : "l"(a), "l"(b)); return r;
}
__device__ __forceinline__ float getf(const float4& v, int j) {
    switch (j) { case 0: return v.x; case 1: return v.y;
                 case 2: return v.z; default: return v.w; }
}

// Y[i][o] = bias[o] + sum_k sum_c X[nbr[i][k]][c] * W[k][c][o]
//
// Lane l: m = l&3 (channel-quad), h = (l>>2)&1 (output-half), ns = l>>3
// (node octet). Lane accumulates partials over channels [4m,4m+4) x outputs
// [8h,8h+8) for 8 nodes. Weight smem: conflict-free 16B-stride lane classes.
//
// R9 (scheduling only; traffic already at structural floor):
//  - next-k index LDS issued right after this k's LDGs (latency overlaps
//    compute; next iteration's gathers fire with zero address stall)
//  - compute j-outer in two jj-pair passes: first FFMA depends only on
//    xc[0], so compute drains as gather returns stagger in.

__global__ __launch_bounds__(TPB, 4)
void conv_kernel(const float* __restrict__ x,       // [N_in, 16]
                 const float* __restrict__ w,       // [27, 16, 16]
                 const float* __restrict__ bias,    // [16]
                 const int*   __restrict__ nbr,     // [N_out, 27]
                 float*       __restrict__ out,     // [N_out, 16]
                 int n_out,
                 const int*   __restrict__ lvl,
                 long long tail_start, int tail_count)
{
    __shared__ __align__(16) float ws[KK * 256];    // 27648 B, permuted
    __shared__ __align__(16) int idxT[KK * NPB];    // 13824 B, [k][node]

    // tail passthrough for flattened (out, level) tuple
    if (blockIdx.x == 0 && lvl != nullptr && (int)threadIdx.x < tail_count)
        out[tail_start + threadIdx.x] = (float)(*lvl);

    // Stage weights permuted (conflict-free 16B-stride lane classes):
    //   i = k*256 + c*16 + o;  jj=c&3, q=(c>>2)+4*(o>>3), e=o&7
    //   ws[k*256 + jj*64 + (e>>2)*32 + q*4 + (e&3)] = w[i]
    for (int i = threadIdx.x; i < KK * 256; i += TPB) {
        int k = i >> 8, c = (i >> 4) & 15, o = i & 15;
        int jj = c & 3, q = (c >> 2) + 4 * (o >> 3), e = o & 7;
        ws[k * 256 + jj * 64 + (e >> 2) * 32 + q * 4 + (e & 3)] = w[i];
    }
    // Stage indices transposed: idxT[k][node_local] (coalesced gmem reads)
    const int base = blockIdx.x * NPB;
    for (int i = threadIdx.x; i < KK * NPB; i += TPB) {
        int nl = i / KK, kk = i - nl * KK;
        int node = base + nl;
        if (node >= n_out) node = n_out - 1;
        idxT[kk * NPB + nl] = __ldcg(&nbr[(long long)node * KK + kk]);
    }
    __syncthreads();

    const int warp = threadIdx.x >> 5;
    const int lane = threadIdx.x & 31;
    const int warpbase = base + warp * 32;
    if (warpbase >= n_out) return;
    const int m  = lane & 3;
    const int h  = (lane >> 2) & 1;
    const int ns = lane >> 3;
    const int nlb = warp * 32 + ns * 8;             // local node base (8)
    const int q4 = (m + 4 * h) * 4;                 // lane-class float offset

    ull acc[8][4];                                   // [node][out-pair]
#pragma unroll
    for (int j = 0; j < 8; ++j)
#pragma unroll
        for (int p = 0; p < 4; ++p) acc[j][p] = 0ull;

    // indices for k=0
    int4 ia = *reinterpret_cast<const int4*>(idxT + nlb);
    int4 ib = *reinterpret_cast<const int4*>(idxT + nlb + 4);

#pragma unroll 1
    for (int k = 0; k < KK; ++k) {
        // issue this k's 8 gathers (MLP=8, L2-only)
        float4 xc[8];
        xc[0] = __ldcg(reinterpret_cast<const float4*>(x + (size_t)ia.x * 16) + m);
        xc[1] = __ldcg(reinterpret_cast<const float4*>(x + (size_t)ia.y * 16) + m);
        xc[2] = __ldcg(reinterpret_cast<const float4*>(x + (size_t)ia.z * 16) + m);
        xc[3] = __ldcg(reinterpret_cast<const float4*>(x + (size_t)ia.w * 16) + m);
        xc[4] = __ldcg(reinterpret_cast<const float4*>(x + (size_t)ib.x * 16) + m);
        xc[5] = __ldcg(reinterpret_cast<const float4*>(x + (size_t)ib.y * 16) + m);
        xc[6] = __ldcg(reinterpret_cast<const float4*>(x + (size_t)ib.z * 16) + m);
        xc[7] = __ldcg(reinterpret_cast<const float4*>(x + (size_t)ib.w * 16) + m);

        // prefetch next k's indices (LDS latency hides under compute)
        const int kn = (k + 1 < KK) ? (k + 1) : (KK - 1);
        ia = *reinterpret_cast<const int4*>(idxT + kn * NPB + nlb);
        ib = *reinterpret_cast<const int4*>(idxT + kn * NPB + nlb + 4);

        const float* wk = ws + k * 256 + q4;

        // pass 0: channels jj = 0,1 ; j-outer so first FFMA needs only xc[0]
        {
            ulonglong2 wA0 = *reinterpret_cast<const ulonglong2*>(wk);
            ulonglong2 wB0 = *reinterpret_cast<const ulonglong2*>(wk + 32);
            ulonglong2 wA1 = *reinterpret_cast<const ulonglong2*>(wk + 64);
            ulonglong2 wB1 = *reinterpret_cast<const ulonglong2*>(wk + 96);
#pragma unroll
            for (int j = 0; j < 8; ++j) {
                const ull a0 = splat2(getf(xc[j], 0));
                ffma2(acc[j][0], a0, wA0.x);
                ffma2(acc[j][1], a0, wA0.y);
                ffma2(acc[j][2], a0, wB0.x);
                ffma2(acc[j][3], a0, wB0.y);
                const ull a1 = splat2(getf(xc[j], 1));
                ffma2(acc[j][0], a1, wA1.x);
                ffma2(acc[j][1], a1, wA1.y);
                ffma2(acc[j][2], a1, wB1.x);
                ffma2(acc[j][3], a1, wB1.y);
            }
        }
        // pass 1: channels jj = 2,3
        {
            ulonglong2 wA2 = *reinterpret_cast<const ulonglong2*>(wk + 128);
            ulonglong2 wB2 = *reinterpret_cast<const ulonglong2*>(wk + 160);
            ulonglong2 wA3 = *reinterpret_cast<const ulonglong2*>(wk + 192);
            ulonglong2 wB3 = *reinterpret_cast<const ulonglong2*>(wk + 224);
#pragma unroll
            for (int j = 0; j < 8; ++j) {
                const ull a2 = splat2(getf(xc[j], 2));
                ffma2(acc[j][0], a2, wA2.x);
                ffma2(acc[j][1], a2, wA2.y);
                ffma2(acc[j][2], a2, wB2.x);
                ffma2(acc[j][3], a2, wB2.y);
                const ull a3 = splat2(getf(xc[j], 3));
                ffma2(acc[j][0], a3, wA3.x);
                ffma2(acc[j][1], a3, wA3.y);
                ffma2(acc[j][2], a3, wB3.x);
                ffma2(acc[j][3], a3, wB3.y);
            }
        }
    }

    // Epilogue: reduce channel-quad partials over the 4 m-lanes, add bias.
    float4 b0 = __ldg(reinterpret_cast<const float4*>(bias) + 2 * h);
    float4 b1 = __ldg(reinterpret_cast<const float4*>(bias) + 2 * h + 1);
    ull bp[4] = { pack2(b0.x, b0.y), pack2(b0.z, b0.w),
                  pack2(b1.x, b1.y), pack2(b1.z, b1.w) };

#pragma unroll
    for (int j = 0; j < 8; ++j) {
#pragma unroll
        for (int p = 0; p < 4; ++p) {
            ull v = acc[j][p];
            v = addp2(v, __shfl_xor_sync(0xffffffffu, v, 1));
            v = addp2(v, __shfl_xor_sync(0xffffffffu, v, 2));
            acc[j][p] = v;
        }
        const int node = warpbase + ns * 8 + j;
        if (m == 0 && node < n_out) {
            ulonglong2* op = reinterpret_cast<ulonglong2*>(
                out + (long long)node * 16 + 8 * h);
            ulonglong2 s0; s0.x = addp2(acc[j][0], bp[0]);
                           s0.y = addp2(acc[j][1], bp[1]);
            ulonglong2 s1; s1.x = addp2(acc[j][2], bp[2]);
                           s1.y = addp2(acc[j][3], bp[3]);
            op[0] = s0;
            op[1] = s1;
        }
    }
}

extern "C" void kernel_launch(void* const* d_in, const int* in_sizes, int n_in,
                              void* d_out, int out_size)
{
    const float* x    = (const float*)d_in[0];
    const float* w    = (const float*)d_in[1];
    const float* bias = (const float*)d_in[2];
    const int*   nbr  = (const int*)d_in[3];
    const int*   lvl  = (n_in > 4) ? (const int*)d_in[4] : nullptr;

    const int n_out = in_sizes[3] / KK;
    float* out = (float*)d_out;

    const long long conv_elems = (long long)n_out * 16;
    long long tail_start = conv_elems;
    int tail_count = 0;
    if ((long long)out_size > conv_elems && lvl != nullptr)
        tail_count = (int)((long long)out_size - conv_elems);

    const int grid = (n_out + NPB - 1) / NPB;
    conv_kernel<<<grid, TPB>>>(x, w, bias, nbr, out, n_out,
                               lvl, tail_start, tail_count);
}